// round 16
// baseline (speedup 1.0000x reference)
#include <cuda_runtime.h>
#include <cuda_fp16.h>
#include <math.h>
#include <stdint.h>

// Problem constants
#define Bsz   4
#define Lseq  4096
#define Dmod  1024
#define Hn    16
#define HDim  64
#define CH    128
#define NCH   32
#define Mrows (Bsz*Lseq)          // 16384
#define NBH   (Bsz*Hn)            // 64
#define EPSC  1e-12f

// Scratch (device globals — allocation-free per harness rules)
__device__ __half g_q[(size_t)NBH*Lseq*HDim];        // (b,h,l,d) fp16
__device__ __half g_k[(size_t)NBH*Lseq*HDim];
__device__ __half g_v[(size_t)NBH*Lseq*HDim];
__device__ __half g_attn[(size_t)Bsz*Lseq*Dmod];     // (b,l,D) fp16
__device__ __half g_xt[(size_t)Mrows*Dmod];          // X in fp16
__device__ __half g_wt[(size_t)4*Dmod*Dmod];         // Wq,Wk,Wv,Wo fp16
// chunk-scan state (fp32, TRANSPOSED e-major: S^T[e][d])
__device__ float g_Sloc[(size_t)NBH*NCH*HDim*HDim];
__device__ float g_Spre[(size_t)NBH*NCH*HDim*HDim];
__device__ float g_zloc[(size_t)NBH*NCH*HDim];
__device__ float g_zpre[(size_t)NBH*NCH*HDim];

// ---------------------------------------------------------------------------
// PTX helpers
// ---------------------------------------------------------------------------
__device__ __forceinline__ uint32_t smem_u32(const void* p) {
    uint32_t a;
    asm("{ .reg .u64 t; cvta.to.shared.u64 t, %1; cvt.u32.u64 %0, t; }" : "=r"(a) : "l"(p));
    return a;
}
__device__ __forceinline__ uint32_t pack_h2(float a, float b) {
    __half2 h = __floats2half2_rn(a, b);
    return *(uint32_t*)&h;
}
__device__ __forceinline__ void cp_async16(uint32_t smem, const void* g) {
    asm volatile("cp.async.cg.shared.global [%0], [%1], 16;" :: "r"(smem), "l"(g));
}
#define CP_COMMIT() asm volatile("cp.async.commit_group;" ::: "memory")
#define CP_WAIT1()  asm volatile("cp.async.wait_group 1;" ::: "memory")

__device__ __forceinline__ void mma_f16(float& c0, float& c1, float& c2, float& c3,
                                        uint32_t a0, uint32_t a1, uint32_t a2, uint32_t a3,
                                        uint32_t b0, uint32_t b1) {
    asm volatile(
        "mma.sync.aligned.m16n8k16.row.col.f32.f16.f16.f32 "
        "{%0,%1,%2,%3}, {%4,%5,%6,%7}, {%8,%9}, {%0,%1,%2,%3};"
        : "+f"(c0), "+f"(c1), "+f"(c2), "+f"(c3)
        : "r"(a0), "r"(a1), "r"(a2), "r"(a3), "r"(b0), "r"(b1));
}
__device__ __forceinline__ void ldsm4(uint32_t* r, uint32_t addr) {
    asm volatile("ldmatrix.sync.aligned.m8n8.x4.shared.b16 {%0,%1,%2,%3}, [%4];"
                 : "=r"(r[0]), "=r"(r[1]), "=r"(r[2]), "=r"(r[3]) : "r"(addr));
}

// ---------------------------------------------------------------------------
// One-time fp16 conversion of X and the four weight matrices.
// ---------------------------------------------------------------------------
#define XN8 (Mrows*Dmod/8)
#define WN8 (Dmod*Dmod/8)
#define TOTN8 (XN8 + 4*WN8)

__global__ __launch_bounds__(256) void conv_fp16(const float4* __restrict__ x,
                                                 const float4* __restrict__ wq,
                                                 const float4* __restrict__ wk,
                                                 const float4* __restrict__ wv,
                                                 const float4* __restrict__ wo) {
    const int stride = gridDim.x * blockDim.x;
    for (int i = blockIdx.x * blockDim.x + threadIdx.x; i < TOTN8; i += stride) {
        const float4* src;
        uint4* dst;
        if (i < XN8) {
            src = x + (size_t)i * 2;
            dst = (uint4*)g_xt + i;
        } else {
            const int r = i - XN8;
            const int w = r >> 17;
            const int off = r & (WN8 - 1);
            const float4* s = (w == 0) ? wq : (w == 1) ? wk : (w == 2) ? wv : wo;
            src = s + (size_t)off * 2;
            dst = (uint4*)g_wt + (size_t)w * WN8 + off;
        }
        float4 lo = __ldg(src);
        float4 hi = __ldg(src + 1);
        *dst = make_uint4(pack_h2(lo.x, lo.y), pack_h2(lo.z, lo.w),
                          pack_h2(hi.x, hi.y), pack_h2(hi.z, hi.w));
    }
}

// ---------------------------------------------------------------------------
// fp16 m16n8k16 GEMM: C[m][n] = sum_k A[m][k] * W[n][k]
// CTA 128x128, BK=64, 8 warps (2x4 -> 64x32 warp tiles).
// cp.async 3-stage pipeline; B fragments k-paired into ldsm4 (one x4 covers
// two consecutive k16 steps of an n8 tile — same pattern as the A operand).
// ---------------------------------------------------------------------------
#define BKH 64
#define LDPH 72
#define TILE_HALVES (128 * LDPH)
#define STAGE_HALVES (2 * TILE_HALVES)
#define STAGE_BYTES (STAGE_HALVES * 2)      // 36864
#define NSTAGE 3
#define GEMM_SMEM_BYTES (NSTAGE * STAGE_BYTES)  // 110592

__global__ __launch_bounds__(256, 2) void mma_gemm(float* __restrict__ OutPlain,
                                                   int mode) {
    extern __shared__ __align__(16) __half smh[];
    const uint32_t smb = smem_u32(smh);

    const int tid  = threadIdx.x;
    const int wid  = tid >> 5;
    const int lane = tid & 31;
    const int g    = lane >> 2;
    const int t    = lane & 3;

    const int w = blockIdx.z;
    const __half* A  = (mode == 1) ? g_attn : g_xt;
    const __half* Wm = g_wt + (size_t)((mode == 1) ? 3 : w) * Dmod * Dmod;
    __half* outp = (w == 0) ? g_q : (w == 1) ? g_k : g_v;

    const int rowBase = blockIdx.y * 128;
    const int colBase = blockIdx.x * 128;
    const int mBase = (wid >> 2) * 64;
    const int nBase = (wid & 3) * 32;

    // loader: 4 rows (stride 32) x one 16B group per thread per matrix
    const int ldRow = tid >> 3;
    const int ldC8  = tid & 7;
    const __half* aG = A  + (size_t)(rowBase + ldRow) * Dmod + ldC8 * 8;
    const __half* bG = Wm + (size_t)(colBase + ldRow) * Dmod + ldC8 * 8;
    uint32_t stDst[4];
    #pragma unroll
    for (int i = 0; i < 4; ++i)
        stDst[i] = smb + 2u * ((uint32_t)(ldRow + 32 * i) * LDPH + ldC8 * 8);

    // ldmatrix per-thread base addresses (stage 0)
    const int l15 = lane & 15;
    const int hi8 = (lane >> 4) * 8;       // A x4: col group
    const int l7  = lane & 7;
    const int q8  = (lane >> 3) * 8;       // B k-pair x4: col group 0/8/16/24
    uint32_t aAddr[4], bAddr[4];
    #pragma unroll
    for (int mi = 0; mi < 4; ++mi)
        aAddr[mi] = smb + 2u * ((uint32_t)(mBase + mi * 16 + l15) * LDPH + hi8);
    #pragma unroll
    for (int ni = 0; ni < 4; ++ni)
        bAddr[ni] = smb + (uint32_t)TILE_HALVES * 2u
                  + 2u * ((uint32_t)(nBase + ni * 8 + l7) * LDPH + q8);

    float acc[4][4][4];
    #pragma unroll
    for (int mi = 0; mi < 4; ++mi)
        #pragma unroll
        for (int ni = 0; ni < 4; ++ni)
            #pragma unroll
            for (int j = 0; j < 4; ++j) acc[mi][ni][j] = 0.f;

    const int NKT = Dmod / BKH;   // 16

    auto issue_stage = [&](int kt) {
        const uint32_t sb = (uint32_t)(kt % NSTAGE) * STAGE_BYTES;
        #pragma unroll
        for (int i = 0; i < 4; ++i) {
            cp_async16(stDst[i] + sb, aG + (size_t)(32 * i) * Dmod + kt * BKH);
            cp_async16(stDst[i] + sb + TILE_HALVES * 2, bG + (size_t)(32 * i) * Dmod + kt * BKH);
        }
        CP_COMMIT();
    };

    issue_stage(0);
    issue_stage(1);

    for (int kt = 0; kt < NKT; ++kt) {
        CP_WAIT1();
        __syncthreads();

        const uint32_t sb = (uint32_t)(kt % NSTAGE) * STAGE_BYTES;
        #pragma unroll
        for (int jp = 0; jp < 2; ++jp) {            // k16 pairs
            uint32_t bf[4][4];
            #pragma unroll
            for (int ni = 0; ni < 4; ++ni) ldsm4(bf[ni], bAddr[ni] + sb + jp * 64);
            #pragma unroll
            for (int h = 0; h < 2; ++h) {           // k16 = 2*jp + h
                const uint32_t kb = sb + (uint32_t)(jp * 2 + h) * 32;
                uint32_t af[4][4];
                #pragma unroll
                for (int mi = 0; mi < 4; ++mi) ldsm4(af[mi], aAddr[mi] + kb);
                #pragma unroll
                for (int mi = 0; mi < 4; ++mi)
                    #pragma unroll
                    for (int ni = 0; ni < 4; ++ni)
                        mma_f16(acc[mi][ni][0], acc[mi][ni][1], acc[mi][ni][2], acc[mi][ni][3],
                                af[mi][0], af[mi][1], af[mi][2], af[mi][3],
                                bf[ni][2 * h], bf[ni][2 * h + 1]);
            }
        }
        if (kt + 2 < NKT) issue_stage(kt + 2);
        else CP_COMMIT();   // empty group keeps wait_group count invariant
    }

    const bool do_elu = (mode == 0) && (w < 2);
    #pragma unroll
    for (int mi = 0; mi < 4; ++mi) {
        #pragma unroll
        for (int ni = 0; ni < 4; ++ni) {
            const int m0 = rowBase + mBase + mi * 16 + g;
            const int n  = colBase + nBase + ni * 8 + 2 * t;
            #pragma unroll
            for (int half_ = 0; half_ < 2; ++half_) {
                const int m = m0 + half_ * 8;
                float v0 = acc[mi][ni][2 * half_ + 0];
                float v1 = acc[mi][ni][2 * half_ + 1];
                if (do_elu) {
                    v0 = (v0 > 0.f) ? (v0 + 1.f) : expf(v0);
                    v1 = (v1 > 0.f) ? (v1 + 1.f) : expf(v1);
                }
                if (mode == 0) {
                    const int hh = n >> 6;
                    const int dd = n & 63;
                    const int bb = m >> 12;
                    const int ll = m & (Lseq - 1);
                    __half* dst = outp + (((size_t)(bb * Hn + hh) * Lseq + ll) * HDim + dd);
                    *(uint32_t*)dst = pack_h2(v0, v1);
                } else {
                    float* dst = OutPlain + (size_t)m * Dmod + n;
                    *(float2*)dst = make_float2(v0, v1);
                }
            }
        }
    }
}

// ---------------------------------------------------------------------------
// Pass 1 (fp16 tensor cores): SlocT[e][d] = sum_s V[s,e] K[s,d], zloc from K.
// B (K) fragments k-paired into ldsm4.
// ---------------------------------------------------------------------------
#define LTH 136
#define P1_SMEM_BYTES (2 * 64 * LTH * 2)   // 34816

__global__ __launch_bounds__(128) void attn_local() {
    extern __shared__ __align__(16) __half smh[];
    const uint32_t smb = smem_u32(smh);
    __half* Vt = smh;               // [e][s] 64 x 136
    __half* Kt = smh + 64 * LTH;    // [d][s] 64 x 136

    const int tid  = threadIdx.x;
    const int w    = tid >> 5;
    const int lane = tid & 31;
    const int g    = lane >> 2;
    const int t    = lane & 3;
    const int l15 = lane & 15;
    const int hi8 = (lane >> 4) * 8;
    const int l7  = lane & 7;
    const int q8  = (lane >> 3) * 8;

    const int bc = blockIdx.x;
    const int bh = bc >> 5;
    const int c  = bc & 31;

    const __half* gk = g_k + ((size_t)bh * Lseq + (size_t)c * CH) * HDim;
    const __half* gv = g_v + ((size_t)bh * Lseq + (size_t)c * CH) * HDim;

    #pragma unroll
    for (int it = 0; it < 8; ++it) {
        int task = tid + 128 * it;           // 0..1023
        int e = task & 63, s8 = task >> 6;   // s8: 0..15
        uint32_t p[4];
        #pragma unroll
        for (int j = 0; j < 4; ++j) {
            __half a = __ldg(gv + (size_t)(s8 * 8 + 2 * j + 0) * HDim + e);
            __half b = __ldg(gv + (size_t)(s8 * 8 + 2 * j + 1) * HDim + e);
            p[j] = *(uint16_t*)&a | ((uint32_t)*(uint16_t*)&b << 16);
        }
        *(uint4*)(Vt + e * LTH + s8 * 8) = make_uint4(p[0], p[1], p[2], p[3]);
        #pragma unroll
        for (int j = 0; j < 4; ++j) {
            __half a = __ldg(gk + (size_t)(s8 * 8 + 2 * j + 0) * HDim + e);
            __half b = __ldg(gk + (size_t)(s8 * 8 + 2 * j + 1) * HDim + e);
            p[j] = *(uint16_t*)&a | ((uint32_t)*(uint16_t*)&b << 16);
        }
        *(uint4*)(Kt + e * LTH + s8 * 8) = make_uint4(p[0], p[1], p[2], p[3]);
    }
    __syncthreads();

    {
        const int d = tid >> 1, hf = tid & 1;
        const __half2* kr = (const __half2*)(Kt + d * LTH + hf * 64);
        float zs = 0.f;
        #pragma unroll
        for (int s = 0; s < 32; ++s) {
            float2 f = __half22float2(kr[s]);
            zs += f.x + f.y;
        }
        zs += __shfl_xor_sync(0xffffffffu, zs, 1);
        if (hf == 0) g_zloc[(size_t)bc * HDim + d] = zs;
    }

    const int r0 = w * 16 + g;
    const int r1 = r0 + 8;
    const uint32_t avBase = smb + 2u * ((uint32_t)(w * 16 + l15) * LTH + hi8);
    const uint32_t bkBase = smb + 2u * ((uint32_t)(64 * LTH) + (uint32_t)l7 * LTH + q8);

    float acc[8][4];
    #pragma unroll
    for (int ni = 0; ni < 8; ++ni)
        #pragma unroll
        for (int j = 0; j < 4; ++j) acc[ni][j] = 0.f;

    #pragma unroll
    for (int jp = 0; jp < 4; ++jp) {          // pairs of k16 steps
        uint32_t av0[4], av1[4];
        ldsm4(av0, avBase + (2 * jp + 0) * 32);
        ldsm4(av1, avBase + (2 * jp + 1) * 32);
        #pragma unroll
        for (int ni = 0; ni < 8; ++ni) {
            uint32_t bk4[4];
            ldsm4(bk4, bkBase + (uint32_t)(ni * 8 * LTH) * 2 + jp * 64);
            mma_f16(acc[ni][0], acc[ni][1], acc[ni][2], acc[ni][3],
                    av0[0], av0[1], av0[2], av0[3], bk4[0], bk4[1]);
            mma_f16(acc[ni][0], acc[ni][1], acc[ni][2], acc[ni][3],
                    av1[0], av1[1], av1[2], av1[3], bk4[2], bk4[3]);
        }
    }

    float* So = g_Sloc + (size_t)bc * (HDim * HDim);
    #pragma unroll
    for (int ni = 0; ni < 8; ++ni) {
        const int d0 = ni * 8 + 2 * t;
        *(float2*)(So + (size_t)r0 * HDim + d0) = make_float2(acc[ni][0], acc[ni][1]);
        *(float2*)(So + (size_t)r1 * HDim + d0) = make_float2(acc[ni][2], acc[ni][3]);
    }
}

// ---------------------------------------------------------------------------
// Pass 2: exclusive prefix over 32 chunks, 4-way split, software-pipelined.
// ---------------------------------------------------------------------------
__global__ __launch_bounds__(256) void attn_scan() {
    const int tid = threadIdx.x;
    const int bh  = blockIdx.x >> 2;
    const int qt  = blockIdx.x & 3;
    const int eoff = qt * 1024 + tid * 4;
    const bool doz = (qt == 0) && (tid < HDim);

    const size_t base0 = (size_t)bh * NCH * (HDim * HDim);
    const size_t zb0   = (size_t)bh * NCH * HDim + tid;

    float4 acc = make_float4(0.f, 0.f, 0.f, 0.f);
    float accz = 0.f;
    float4 nxt = *(const float4*)(g_Sloc + base0 + eoff);
    float nz = doz ? g_zloc[zb0] : 0.f;

    for (int c = 0; c < NCH; ++c) {
        const size_t base = base0 + (size_t)c * (HDim * HDim);
        float4 cur = nxt;
        float cz = nz;
        if (c + 1 < NCH) {
            nxt = *(const float4*)(g_Sloc + base + (HDim * HDim) + eoff);
            if (doz) nz = g_zloc[zb0 + (size_t)(c + 1) * HDim];
        }
        *(float4*)(g_Spre + base + eoff) = acc;
        acc.x += cur.x; acc.y += cur.y; acc.z += cur.z; acc.w += cur.w;
        if (doz) {
            g_zpre[zb0 + (size_t)c * HDim] = accz;
            accz += cz;
        }
    }
}

// ---------------------------------------------------------------------------
// Pass 3: per-(bh,chunk) output, all-fp16 mma, k-paired B loads.
// 256 threads = 8 warps, 2 CTAs/SM.
// ---------------------------------------------------------------------------
#define LQH 72
#define LSH 136
#define HQ  0
#define HK  (HQ + 128*LQH)
#define HS  (HK + 128*LQH)
#define HV  (HS + 128*LSH)
#define HP  (HV + 64*LSH)
#define HEND (HP + 64*LQH)
#define FZ  (HEND/2)
#define FDN (FZ + 64)
#define AO_SMEM_BYTES ((FDN + 128) * 4)   // 99072

__global__ __launch_bounds__(256, 2) void attn_out() {
    extern __shared__ __align__(16) __half smh[];
    const uint32_t smb = smem_u32(smh);
    float* smf = (float*)smh;

    const int tid  = threadIdx.x;
    const int w    = tid >> 5;
    const int lane = tid & 31;
    const int g    = lane >> 2;
    const int t    = lane & 3;
    const int l15 = lane & 15;
    const int hi8 = (lane >> 4) * 8;
    const int l7  = lane & 7;
    const int q8  = (lane >> 3) * 8;

    const int bc = blockIdx.x;
    const int bh = bc >> 5;
    const int c  = bc & 31;

    const __half* gq = g_q + ((size_t)bh * Lseq + (size_t)c * CH) * HDim;
    const __half* gk = g_k + ((size_t)bh * Lseq + (size_t)c * CH) * HDim;
    const __half* gv = g_v + ((size_t)bh * Lseq + (size_t)c * CH) * HDim;
    const float* Sp = g_Spre + (size_t)bc * HDim * HDim;
    const float* zp = g_zpre + (size_t)bc * HDim;
    __half* ga = g_attn + (size_t)(bh >> 4) * Lseq * Dmod
                        + ((size_t)c * CH) * Dmod + (size_t)(bh & 15) * HDim;

    #pragma unroll
    for (int it = 0; it < 4; ++it) {
        int idx = tid + 256 * it;
        int row = idx >> 3, c8 = idx & 7;
        *(uint4*)(smh + HQ + row * LQH + c8 * 8) = __ldg((const uint4*)gq + idx);
        *(uint4*)(smh + HK + row * LQH + c8 * 8) = __ldg((const uint4*)gk + idx);
    }
    #pragma unroll
    for (int it = 0; it < 4; ++it) {
        int task = tid + 256 * it;
        int e = task & 63, s8 = task >> 6;
        uint32_t p[4];
        #pragma unroll
        for (int j = 0; j < 4; ++j) {
            __half a = __ldg(gv + (size_t)(s8 * 8 + 2 * j + 0) * HDim + e);
            __half b = __ldg(gv + (size_t)(s8 * 8 + 2 * j + 1) * HDim + e);
            p[j] = *(uint16_t*)&a | ((uint32_t)*(uint16_t*)&b << 16);
        }
        *(uint4*)(smh + HV + e * LSH + s8 * 8) = make_uint4(p[0], p[1], p[2], p[3]);
    }
    #pragma unroll
    for (int it = 0; it < 4; ++it) {
        int idx = tid + 256 * it;
        int row = idx >> 4, c4 = idx & 15;
        float4 p = __ldg((const float4*)Sp + idx);
        *(uint2*)(smh + HP + row * LQH + c4 * 4) =
            make_uint2(pack_h2(p.x, p.y), pack_h2(p.z, p.w));
    }
    if (tid < HDim) smf[FZ + tid] = __ldg(zp + tid);
    __syncthreads();

    {
        const int r = tid >> 1, hf = tid & 1;
        const __half2* qrow = (const __half2*)(smh + HQ + r * LQH + hf * 32);
        const float* zz = smf + FZ + hf * 32;
        float s = 0.f;
        #pragma unroll
        for (int d = 0; d < 16; ++d) {
            float2 q2 = __half22float2(qrow[d]);
            s += q2.x * zz[2 * d] + q2.y * zz[2 * d + 1];
        }
        s += __shfl_xor_sync(0xffffffffu, s, 1);
        if (hf == 0) smf[FDN + r] = s;
    }

    const int r0 = w * 16 + g;
    const int r1 = r0 + 8;

    const uint32_t aqBase = smb + 2u * ((uint32_t)HQ + (uint32_t)(w * 16 + l15) * LQH + hi8);
    const uint32_t bkBase = smb + 2u * ((uint32_t)HK + (uint32_t)l7 * LQH + q8);
    const uint32_t bpBase = smb + 2u * ((uint32_t)HP + (uint32_t)l7 * LQH + q8);
    const uint32_t asBase = smb + 2u * ((uint32_t)HS + (uint32_t)(w * 16 + l15) * LSH + hi8);
    const uint32_t bvBase = smb + 2u * ((uint32_t)HV + (uint32_t)l7 * LSH + q8);

    uint32_t aq[4][4];
    #pragma unroll
    for (int k16 = 0; k16 < 4; ++k16) ldsm4(aq[k16], aqBase + k16 * 32);

    // ---- mma1: scores = Q K^T (B k-paired: one ldsm4 per ni per k-pair) ----
    float acc1[16][4];
    #pragma unroll
    for (int ni = 0; ni < 16; ++ni)
        #pragma unroll
        for (int j = 0; j < 4; ++j) acc1[ni][j] = 0.f;

    #pragma unroll
    for (int jp = 0; jp < 2; ++jp) {
        #pragma unroll
        for (int ni = 0; ni < 16; ++ni) {
            uint32_t bk4[4];
            ldsm4(bk4, bkBase + (uint32_t)(ni * 8 * LQH) * 2 + jp * 64);
            mma_f16(acc1[ni][0], acc1[ni][1], acc1[ni][2], acc1[ni][3],
                    aq[2*jp][0], aq[2*jp][1], aq[2*jp][2], aq[2*jp][3],
                    bk4[0], bk4[1]);
            mma_f16(acc1[ni][0], acc1[ni][1], acc1[ni][2], acc1[ni][3],
                    aq[2*jp+1][0], aq[2*jp+1][1], aq[2*jp+1][2], aq[2*jp+1][3],
                    bk4[2], bk4[3]);
        }
    }

    float rs0 = 0.f, rs1 = 0.f;
    #pragma unroll
    for (int ni = 0; ni < 16; ++ni) {
        const int cb = ni * 8 + 2 * t;
        float m0 = (cb     <= r0) ? acc1[ni][0] : 0.f;
        float m1 = (cb + 1 <= r0) ? acc1[ni][1] : 0.f;
        float m2 = (cb     <= r1) ? acc1[ni][2] : 0.f;
        float m3 = (cb + 1 <= r1) ? acc1[ni][3] : 0.f;
        rs0 += m0 + m1;
        rs1 += m2 + m3;
        *(uint32_t*)(smh + HS + r0 * LSH + cb) = pack_h2(m0, m1);
        *(uint32_t*)(smh + HS + r1 * LSH + cb) = pack_h2(m2, m3);
    }
    rs0 += __shfl_xor_sync(0xffffffffu, rs0, 1);
    rs0 += __shfl_xor_sync(0xffffffffu, rs0, 2);
    rs1 += __shfl_xor_sync(0xffffffffu, rs1, 1);
    rs1 += __shfl_xor_sync(0xffffffffu, rs1, 2);
    __syncwarp();
    if (t == 0) {
        smf[FDN + r0] = 1.f / (smf[FDN + r0] + rs0);
        smf[FDN + r1] = 1.f / (smf[FDN + r1] + rs1);
    }
    __syncwarp();
    const float inv0 = smf[FDN + r0];
    const float inv1 = smf[FDN + r1];

    // ---- mma-pre: accO = Q S_pre (B k-paired) ----
    float accO[8][4];
    #pragma unroll
    for (int ni = 0; ni < 8; ++ni)
        #pragma unroll
        for (int j = 0; j < 4; ++j) accO[ni][j] = 0.f;

    #pragma unroll
    for (int jp = 0; jp < 2; ++jp) {
        #pragma unroll
        for (int ni = 0; ni < 8; ++ni) {
            uint32_t bp4[4];
            ldsm4(bp4, bpBase + (uint32_t)(ni * 8 * LQH) * 2 + jp * 64);
            mma_f16(accO[ni][0], accO[ni][1], accO[ni][2], accO[ni][3],
                    aq[2*jp][0], aq[2*jp][1], aq[2*jp][2], aq[2*jp][3],
                    bp4[0], bp4[1]);
            mma_f16(accO[ni][0], accO[ni][1], accO[ni][2], accO[ni][3],
                    aq[2*jp+1][0], aq[2*jp+1][1], aq[2*jp+1][2], aq[2*jp+1][3],
                    bp4[2], bp4[3]);
        }
    }

    // ---- mma2: accO += scores V (B k-paired over the s dimension) ----
    #pragma unroll
    for (int jp = 0; jp < 4; ++jp) {
        uint32_t as0[4], as1[4];
        ldsm4(as0, asBase + (2 * jp + 0) * 32);
        ldsm4(as1, asBase + (2 * jp + 1) * 32);
        #pragma unroll
        for (int ni = 0; ni < 8; ++ni) {
            uint32_t bv4[4];
            ldsm4(bv4, bvBase + (uint32_t)(ni * 8 * LSH) * 2 + jp * 64);
            mma_f16(accO[ni][0], accO[ni][1], accO[ni][2], accO[ni][3],
                    as0[0], as0[1], as0[2], as0[3], bv4[0], bv4[1]);
            mma_f16(accO[ni][0], accO[ni][1], accO[ni][2], accO[ni][3],
                    as1[0], as1[1], as1[2], as1[3], bv4[2], bv4[3]);
        }
    }

    #pragma unroll
    for (int ni = 0; ni < 8; ++ni) {
        const int e0 = ni * 8 + 2 * t;
        uint32_t o0 = pack_h2(accO[ni][0] * inv0 + EPSC, accO[ni][1] * inv0 + EPSC);
        uint32_t o1 = pack_h2(accO[ni][2] * inv1 + EPSC, accO[ni][3] * inv1 + EPSC);
        *(uint32_t*)(ga + (size_t)r0 * Dmod + e0) = o0;
        *(uint32_t*)(ga + (size_t)r1 * Dmod + e0) = o1;
    }
}

// ---------------------------------------------------------------------------
extern "C" void kernel_launch(void* const* d_in, const int* in_sizes, int n_in,
                              void* d_out, int out_size) {
    const float* x  = (const float*)d_in[0];
    const float* Wq = (const float*)d_in[1];
    const float* Wk = (const float*)d_in[2];
    const float* Wv = (const float*)d_in[3];
    const float* Wo = (const float*)d_in[4];
    float* out = (float*)d_out;

    cudaFuncSetAttribute(mma_gemm, cudaFuncAttributeMaxDynamicSharedMemorySize,
                         GEMM_SMEM_BYTES);
    cudaFuncSetAttribute(attn_local, cudaFuncAttributeMaxDynamicSharedMemorySize,
                         P1_SMEM_BYTES);
    cudaFuncSetAttribute(attn_out, cudaFuncAttributeMaxDynamicSharedMemorySize,
                         AO_SMEM_BYTES);

    conv_fp16<<<2048, 256>>>((const float4*)x, (const float4*)Wq,
                             (const float4*)Wk, (const float4*)Wv,
                             (const float4*)Wo);
    mma_gemm<<<dim3(Dmod / 128, Mrows / 128, 3), 256, GEMM_SMEM_BYTES>>>(nullptr, 0);
    attn_local<<<NBH * NCH, 128, P1_SMEM_BYTES>>>();
    attn_scan<<<NBH * 4, 256>>>();
    attn_out<<<NBH * NCH, 256, AO_SMEM_BYTES>>>();
    mma_gemm<<<dim3(Dmod / 128, Mrows / 128, 1), 256, GEMM_SMEM_BYTES>>>(out, 1);
}

// round 17
// speedup vs baseline: 1.0114x; 1.0114x over previous
#include <cuda_runtime.h>
#include <cuda_fp16.h>
#include <math.h>
#include <stdint.h>

// Problem constants
#define Bsz   4
#define Lseq  4096
#define Dmod  1024
#define Hn    16
#define HDim  64
#define CH    128
#define NCH   32
#define Mrows (Bsz*Lseq)          // 16384
#define NBH   (Bsz*Hn)            // 64
#define EPSC  1e-12f

// Scratch (device globals — allocation-free per harness rules)
__device__ __half g_q[(size_t)NBH*Lseq*HDim];        // (b,h,l,d) fp16
__device__ __half g_k[(size_t)NBH*Lseq*HDim];
__device__ __half g_v[(size_t)NBH*Lseq*HDim];
__device__ __half g_attn[(size_t)Bsz*Lseq*Dmod];     // (b,l,D) fp16
__device__ __half g_xt[(size_t)Mrows*Dmod];          // X in fp16
__device__ __half g_wt[(size_t)4*Dmod*Dmod];         // Wq,Wk,Wv,Wo fp16
// chunk-scan state (fp32, TRANSPOSED e-major: S^T[e][d])
__device__ float g_Sloc[(size_t)NBH*NCH*HDim*HDim];
__device__ float g_Spre[(size_t)NBH*NCH*HDim*HDim];
__device__ float g_zloc[(size_t)NBH*NCH*HDim];
__device__ float g_zpre[(size_t)NBH*NCH*HDim];

// ---------------------------------------------------------------------------
// PTX helpers
// ---------------------------------------------------------------------------
__device__ __forceinline__ uint32_t smem_u32(const void* p) {
    uint32_t a;
    asm("{ .reg .u64 t; cvta.to.shared.u64 t, %1; cvt.u32.u64 %0, t; }" : "=r"(a) : "l"(p));
    return a;
}
__device__ __forceinline__ uint32_t pack_h2(float a, float b) {
    __half2 h = __floats2half2_rn(a, b);
    return *(uint32_t*)&h;
}
__device__ __forceinline__ void cp_async16(uint32_t smem, const void* g) {
    asm volatile("cp.async.cg.shared.global [%0], [%1], 16;" :: "r"(smem), "l"(g));
}
#define CP_COMMIT() asm volatile("cp.async.commit_group;" ::: "memory")
#define CP_WAIT1()  asm volatile("cp.async.wait_group 1;" ::: "memory")
#define CP_WAIT0()  asm volatile("cp.async.wait_group 0;" ::: "memory")

__device__ __forceinline__ void mma_f16(float& c0, float& c1, float& c2, float& c3,
                                        uint32_t a0, uint32_t a1, uint32_t a2, uint32_t a3,
                                        uint32_t b0, uint32_t b1) {
    asm volatile(
        "mma.sync.aligned.m16n8k16.row.col.f32.f16.f16.f32 "
        "{%0,%1,%2,%3}, {%4,%5,%6,%7}, {%8,%9}, {%0,%1,%2,%3};"
        : "+f"(c0), "+f"(c1), "+f"(c2), "+f"(c3)
        : "r"(a0), "r"(a1), "r"(a2), "r"(a3), "r"(b0), "r"(b1));
}
__device__ __forceinline__ void ldsm4(uint32_t* r, uint32_t addr) {
    asm volatile("ldmatrix.sync.aligned.m8n8.x4.shared.b16 {%0,%1,%2,%3}, [%4];"
                 : "=r"(r[0]), "=r"(r[1]), "=r"(r[2]), "=r"(r[3]) : "r"(addr));
}
__device__ __forceinline__ void ldsm2(uint32_t* r, uint32_t addr) {
    asm volatile("ldmatrix.sync.aligned.m8n8.x2.shared.b16 {%0,%1}, [%2];"
                 : "=r"(r[0]), "=r"(r[1]) : "r"(addr));
}

// ---------------------------------------------------------------------------
// One-time fp16 conversion of X and the four weight matrices.
// ---------------------------------------------------------------------------
#define XN8 (Mrows*Dmod/8)
#define WN8 (Dmod*Dmod/8)
#define TOTN8 (XN8 + 4*WN8)

__global__ __launch_bounds__(256) void conv_fp16(const float4* __restrict__ x,
                                                 const float4* __restrict__ wq,
                                                 const float4* __restrict__ wk,
                                                 const float4* __restrict__ wv,
                                                 const float4* __restrict__ wo) {
    const int stride = gridDim.x * blockDim.x;
    for (int i = blockIdx.x * blockDim.x + threadIdx.x; i < TOTN8; i += stride) {
        const float4* src;
        uint4* dst;
        if (i < XN8) {
            src = x + (size_t)i * 2;
            dst = (uint4*)g_xt + i;
        } else {
            const int r = i - XN8;
            const int w = r >> 17;
            const int off = r & (WN8 - 1);
            const float4* s = (w == 0) ? wq : (w == 1) ? wk : (w == 2) ? wv : wo;
            src = s + (size_t)off * 2;
            dst = (uint4*)g_wt + (size_t)w * WN8 + off;
        }
        float4 lo = __ldg(src);
        float4 hi = __ldg(src + 1);
        *dst = make_uint4(pack_h2(lo.x, lo.y), pack_h2(lo.z, lo.w),
                          pack_h2(hi.x, hi.y), pack_h2(hi.z, hi.w));
    }
}

// ---------------------------------------------------------------------------
// fp16 m16n8k16 GEMM: C[m][n] = sum_k A[m][k] * W[n][k]
// CTA 128x128, BK=64, 8 warps (2x4 -> 64x32 warp tiles).
// cp.async 3-stage pipeline, ONE sync + ONE wait per K-tile; prefetch AFTER
// compute (measured faster than prefetch-first: R11=545us vs R14=573us).
// ---------------------------------------------------------------------------
#define BKH 64
#define LDPH 72
#define TILE_HALVES (128 * LDPH)
#define STAGE_HALVES (2 * TILE_HALVES)
#define STAGE_BYTES (STAGE_HALVES * 2)      // 36864
#define NSTAGE 3
#define GEMM_SMEM_BYTES (NSTAGE * STAGE_BYTES)  // 110592

__global__ __launch_bounds__(256, 2) void mma_gemm(float* __restrict__ OutPlain,
                                                   int mode) {
    extern __shared__ __align__(16) __half smh[];
    const uint32_t smb = smem_u32(smh);

    const int tid  = threadIdx.x;
    const int wid  = tid >> 5;
    const int lane = tid & 31;
    const int g    = lane >> 2;
    const int t    = lane & 3;

    const int w = blockIdx.z;
    const __half* A  = (mode == 1) ? g_attn : g_xt;
    const __half* Wm = g_wt + (size_t)((mode == 1) ? 3 : w) * Dmod * Dmod;
    __half* outp = (w == 0) ? g_q : (w == 1) ? g_k : g_v;

    const int rowBase = blockIdx.y * 128;
    const int colBase = blockIdx.x * 128;
    const int mBase = (wid >> 2) * 64;
    const int nBase = (wid & 3) * 32;

    // loader: 4 rows (stride 32) x one 16B group per thread per matrix
    const int ldRow = tid >> 3;
    const int ldC8  = tid & 7;
    const __half* aG = A  + (size_t)(rowBase + ldRow) * Dmod + ldC8 * 8;
    const __half* bG = Wm + (size_t)(colBase + ldRow) * Dmod + ldC8 * 8;
    uint32_t stDst[4];
    #pragma unroll
    for (int i = 0; i < 4; ++i)
        stDst[i] = smb + 2u * ((uint32_t)(ldRow + 32 * i) * LDPH + ldC8 * 8);

    // ldmatrix per-thread base addresses (stage 0)
    const int l15 = lane & 15;
    const int hi8 = (lane >> 4) * 8;
    const int l7  = lane & 7;
    const int b8  = ((lane >> 3) & 1) * 8;
    uint32_t aAddr[4], bAddr[4];
    #pragma unroll
    for (int mi = 0; mi < 4; ++mi)
        aAddr[mi] = smb + 2u * ((uint32_t)(mBase + mi * 16 + l15) * LDPH + hi8);
    #pragma unroll
    for (int ni = 0; ni < 4; ++ni)
        bAddr[ni] = smb + (uint32_t)TILE_HALVES * 2u
                  + 2u * ((uint32_t)(nBase + ni * 8 + l7) * LDPH + b8);

    float acc[4][4][4];
    #pragma unroll
    for (int mi = 0; mi < 4; ++mi)
        #pragma unroll
        for (int ni = 0; ni < 4; ++ni)
            #pragma unroll
            for (int j = 0; j < 4; ++j) acc[mi][ni][j] = 0.f;

    const int NKT = Dmod / BKH;   // 16

    auto issue_stage = [&](int kt) {
        const uint32_t sb = (uint32_t)(kt % NSTAGE) * STAGE_BYTES;
        #pragma unroll
        for (int i = 0; i < 4; ++i) {
            cp_async16(stDst[i] + sb, aG + (size_t)(32 * i) * Dmod + kt * BKH);
            cp_async16(stDst[i] + sb + TILE_HALVES * 2, bG + (size_t)(32 * i) * Dmod + kt * BKH);
        }
        CP_COMMIT();
    };

    issue_stage(0);
    issue_stage(1);

    for (int kt = 0; kt < NKT; ++kt) {
        CP_WAIT1();
        __syncthreads();

        const uint32_t sb = (uint32_t)(kt % NSTAGE) * STAGE_BYTES;
        #pragma unroll
        for (int k16 = 0; k16 < 4; ++k16) {
            const uint32_t kb = sb + k16 * 32;
            uint32_t af[4][4], bf[4][2];
            #pragma unroll
            for (int mi = 0; mi < 4; ++mi) ldsm4(af[mi], aAddr[mi] + kb);
            #pragma unroll
            for (int ni = 0; ni < 4; ++ni) ldsm2(bf[ni], bAddr[ni] + kb);
            #pragma unroll
            for (int mi = 0; mi < 4; ++mi)
                #pragma unroll
                for (int ni = 0; ni < 4; ++ni)
                    mma_f16(acc[mi][ni][0], acc[mi][ni][1], acc[mi][ni][2], acc[mi][ni][3],
                            af[mi][0], af[mi][1], af[mi][2], af[mi][3],
                            bf[ni][0], bf[ni][1]);
        }
        if (kt + 2 < NKT) issue_stage(kt + 2);
        else CP_COMMIT();   // empty group keeps wait_group count invariant
    }

    const bool do_elu = (mode == 0) && (w < 2);
    #pragma unroll
    for (int mi = 0; mi < 4; ++mi) {
        #pragma unroll
        for (int ni = 0; ni < 4; ++ni) {
            const int m0 = rowBase + mBase + mi * 16 + g;
            const int n  = colBase + nBase + ni * 8 + 2 * t;
            #pragma unroll
            for (int half_ = 0; half_ < 2; ++half_) {
                const int m = m0 + half_ * 8;
                float v0 = acc[mi][ni][2 * half_ + 0];
                float v1 = acc[mi][ni][2 * half_ + 1];
                if (do_elu) {
                    v0 = (v0 > 0.f) ? (v0 + 1.f) : expf(v0);
                    v1 = (v1 > 0.f) ? (v1 + 1.f) : expf(v1);
                }
                if (mode == 0) {
                    const int hh = n >> 6;
                    const int dd = n & 63;
                    const int bb = m >> 12;
                    const int ll = m & (Lseq - 1);
                    __half* dst = outp + (((size_t)(bb * Hn + hh) * Lseq + ll) * HDim + dd);
                    *(uint32_t*)dst = pack_h2(v0, v1);
                } else {
                    float* dst = OutPlain + (size_t)m * Dmod + n;
                    *(float2*)dst = make_float2(v0, v1);
                }
            }
        }
    }
}

// ---------------------------------------------------------------------------
// Pass 1 (fp16 tensor cores): SlocT[e][d] = sum_s V[s,e] K[s,d], zloc from K.
// ---------------------------------------------------------------------------
#define LTH 136
#define P1_SMEM_BYTES (2 * 64 * LTH * 2)   // 34816

__global__ __launch_bounds__(128) void attn_local() {
    extern __shared__ __align__(16) __half smh[];
    const uint32_t smb = smem_u32(smh);
    __half* Vt = smh;               // [e][s] 64 x 136
    __half* Kt = smh + 64 * LTH;    // [d][s] 64 x 136

    const int tid  = threadIdx.x;
    const int w    = tid >> 5;
    const int lane = tid & 31;
    const int g    = lane >> 2;
    const int t    = lane & 3;
    const int l15 = lane & 15;
    const int hi8 = (lane >> 4) * 8;
    const int l7  = lane & 7;
    const int b8  = ((lane >> 3) & 1) * 8;

    const int bc = blockIdx.x;
    const int bh = bc >> 5;
    const int c  = bc & 31;

    const __half* gk = g_k + ((size_t)bh * Lseq + (size_t)c * CH) * HDim;
    const __half* gv = g_v + ((size_t)bh * Lseq + (size_t)c * CH) * HDim;

    #pragma unroll
    for (int it = 0; it < 8; ++it) {
        int task = tid + 128 * it;           // 0..1023
        int e = task & 63, s8 = task >> 6;   // s8: 0..15
        uint32_t p[4];
        #pragma unroll
        for (int j = 0; j < 4; ++j) {
            __half a = __ldg(gv + (size_t)(s8 * 8 + 2 * j + 0) * HDim + e);
            __half b = __ldg(gv + (size_t)(s8 * 8 + 2 * j + 1) * HDim + e);
            p[j] = *(uint16_t*)&a | ((uint32_t)*(uint16_t*)&b << 16);
        }
        *(uint4*)(Vt + e * LTH + s8 * 8) = make_uint4(p[0], p[1], p[2], p[3]);
        #pragma unroll
        for (int j = 0; j < 4; ++j) {
            __half a = __ldg(gk + (size_t)(s8 * 8 + 2 * j + 0) * HDim + e);
            __half b = __ldg(gk + (size_t)(s8 * 8 + 2 * j + 1) * HDim + e);
            p[j] = *(uint16_t*)&a | ((uint32_t)*(uint16_t*)&b << 16);
        }
        *(uint4*)(Kt + e * LTH + s8 * 8) = make_uint4(p[0], p[1], p[2], p[3]);
    }
    __syncthreads();

    {
        const int d = tid >> 1, hf = tid & 1;
        const __half2* kr = (const __half2*)(Kt + d * LTH + hf * 64);
        float zs = 0.f;
        #pragma unroll
        for (int s = 0; s < 32; ++s) {
            float2 f = __half22float2(kr[s]);
            zs += f.x + f.y;
        }
        zs += __shfl_xor_sync(0xffffffffu, zs, 1);
        if (hf == 0) g_zloc[(size_t)bc * HDim + d] = zs;
    }

    const int r0 = w * 16 + g;
    const int r1 = r0 + 8;
    const uint32_t avBase = smb + 2u * ((uint32_t)(w * 16 + l15) * LTH + hi8);
    const uint32_t bkBase = smb + 2u * ((uint32_t)(64 * LTH) + (uint32_t)l7 * LTH + b8);

    float acc[8][4];
    #pragma unroll
    for (int ni = 0; ni < 8; ++ni)
        #pragma unroll
        for (int j = 0; j < 4; ++j) acc[ni][j] = 0.f;

    #pragma unroll
    for (int k16 = 0; k16 < 8; ++k16) {
        uint32_t av[4];
        ldsm4(av, avBase + k16 * 32);
        #pragma unroll
        for (int ni = 0; ni < 8; ++ni) {
            uint32_t bk[2];
            ldsm2(bk, bkBase + (uint32_t)(ni * 8 * LTH) * 2 + k16 * 32);
            mma_f16(acc[ni][0], acc[ni][1], acc[ni][2], acc[ni][3],
                    av[0], av[1], av[2], av[3], bk[0], bk[1]);
        }
    }

    float* So = g_Sloc + (size_t)bc * (HDim * HDim);
    #pragma unroll
    for (int ni = 0; ni < 8; ++ni) {
        const int d0 = ni * 8 + 2 * t;
        *(float2*)(So + (size_t)r0 * HDim + d0) = make_float2(acc[ni][0], acc[ni][1]);
        *(float2*)(So + (size_t)r1 * HDim + d0) = make_float2(acc[ni][2], acc[ni][3]);
    }
}

// ---------------------------------------------------------------------------
// Pass 2: exclusive prefix over 32 chunks, 4-way split, software-pipelined.
// ---------------------------------------------------------------------------
__global__ __launch_bounds__(256) void attn_scan() {
    const int tid = threadIdx.x;
    const int bh  = blockIdx.x >> 2;
    const int qt  = blockIdx.x & 3;
    const int eoff = qt * 1024 + tid * 4;
    const bool doz = (qt == 0) && (tid < HDim);

    const size_t base0 = (size_t)bh * NCH * (HDim * HDim);
    const size_t zb0   = (size_t)bh * NCH * HDim + tid;

    float4 acc = make_float4(0.f, 0.f, 0.f, 0.f);
    float accz = 0.f;
    float4 nxt = *(const float4*)(g_Sloc + base0 + eoff);
    float nz = doz ? g_zloc[zb0] : 0.f;

    for (int c = 0; c < NCH; ++c) {
        const size_t base = base0 + (size_t)c * (HDim * HDim);
        float4 cur = nxt;
        float cz = nz;
        if (c + 1 < NCH) {
            nxt = *(const float4*)(g_Sloc + base + (HDim * HDim) + eoff);
            if (doz) nz = g_zloc[zb0 + (size_t)(c + 1) * HDim];
        }
        *(float4*)(g_Spre + base + eoff) = acc;
        acc.x += cur.x; acc.y += cur.y; acc.z += cur.z; acc.w += cur.w;
        if (doz) {
            g_zpre[zb0 + (size_t)c * HDim] = accz;
            accz += cz;
        }
    }
}

// ---------------------------------------------------------------------------
// Pass 3: per-(bh,chunk) output, all-fp16 mma. 256 threads = 8 warps, 2 CTAs/SM.
// Q/K staged via cp.async (overlaps the scalar V-transpose + Sp conversion).
// ---------------------------------------------------------------------------
#define LQH 72
#define LSH 136
#define HQ  0
#define HK  (HQ + 128*LQH)
#define HS  (HK + 128*LQH)
#define HV  (HS + 128*LSH)
#define HP  (HV + 64*LSH)
#define HEND (HP + 64*LQH)
#define FZ  (HEND/2)
#define FDN (FZ + 64)
#define AO_SMEM_BYTES ((FDN + 128) * 4)   // 99072

__global__ __launch_bounds__(256, 2) void attn_out() {
    extern __shared__ __align__(16) __half smh[];
    const uint32_t smb = smem_u32(smh);
    float* smf = (float*)smh;

    const int tid  = threadIdx.x;
    const int w    = tid >> 5;
    const int lane = tid & 31;
    const int g    = lane >> 2;
    const int t    = lane & 3;
    const int l15 = lane & 15;
    const int hi8 = (lane >> 4) * 8;
    const int l7  = lane & 7;
    const int b8  = ((lane >> 3) & 1) * 8;

    const int bc = blockIdx.x;
    const int bh = bc >> 5;
    const int c  = bc & 31;

    const __half* gq = g_q + ((size_t)bh * Lseq + (size_t)c * CH) * HDim;
    const __half* gk = g_k + ((size_t)bh * Lseq + (size_t)c * CH) * HDim;
    const __half* gv = g_v + ((size_t)bh * Lseq + (size_t)c * CH) * HDim;
    const float* Sp = g_Spre + (size_t)bc * HDim * HDim;
    const float* zp = g_zpre + (size_t)bc * HDim;
    __half* ga = g_attn + (size_t)(bh >> 4) * Lseq * Dmod
                        + ((size_t)c * CH) * Dmod + (size_t)(bh & 15) * HDim;

    // ---- stage Q, K via cp.async (DMA overlaps the scalar staging below) ----
    #pragma unroll
    for (int it = 0; it < 4; ++it) {
        int idx = tid + 256 * it;            // 0..1023
        int row = idx >> 3, c8 = idx & 7;
        const uint32_t off = 2u * ((uint32_t)row * LQH + (uint32_t)c8 * 8);
        cp_async16(smb + HQ * 2 + off, (const uint4*)gq + idx);
        cp_async16(smb + HK * 2 + off, (const uint4*)gk + idx);
    }
    CP_COMMIT();

    // ---- stage V transposed (scalar; overlapped with cp.async above) ----
    #pragma unroll
    for (int it = 0; it < 4; ++it) {
        int task = tid + 256 * it;
        int e = task & 63, s8 = task >> 6;
        uint32_t p[4];
        #pragma unroll
        for (int j = 0; j < 4; ++j) {
            __half a = __ldg(gv + (size_t)(s8 * 8 + 2 * j + 0) * HDim + e);
            __half b = __ldg(gv + (size_t)(s8 * 8 + 2 * j + 1) * HDim + e);
            p[j] = *(uint16_t*)&a | ((uint32_t)*(uint16_t*)&b << 16);
        }
        *(uint4*)(smh + HV + e * LSH + s8 * 8) = make_uint4(p[0], p[1], p[2], p[3]);
    }
    // ---- stage S_pre^T (fp32 -> fp16) ----
    #pragma unroll
    for (int it = 0; it < 4; ++it) {
        int idx = tid + 256 * it;
        int row = idx >> 4, c4 = idx & 15;
        float4 p = __ldg((const float4*)Sp + idx);
        *(uint2*)(smh + HP + row * LQH + c4 * 4) =
            make_uint2(pack_h2(p.x, p.y), pack_h2(p.z, p.w));
    }
    if (tid < HDim) smf[FZ + tid] = __ldg(zp + tid);
    CP_WAIT0();
    __syncthreads();

    {
        const int r = tid >> 1, hf = tid & 1;
        const __half2* qrow = (const __half2*)(smh + HQ + r * LQH + hf * 32);
        const float* zz = smf + FZ + hf * 32;
        float s = 0.f;
        #pragma unroll
        for (int d = 0; d < 16; ++d) {
            float2 q2 = __half22float2(qrow[d]);
            s += q2.x * zz[2 * d] + q2.y * zz[2 * d + 1];
        }
        s += __shfl_xor_sync(0xffffffffu, s, 1);
        if (hf == 0) smf[FDN + r] = s;
    }

    const int r0 = w * 16 + g;
    const int r1 = r0 + 8;

    const uint32_t aqBase = smb + 2u * ((uint32_t)HQ + (uint32_t)(w * 16 + l15) * LQH + hi8);
    const uint32_t bkBase = smb + 2u * ((uint32_t)HK + (uint32_t)l7 * LQH + b8);
    const uint32_t bpBase = smb + 2u * ((uint32_t)HP + (uint32_t)l7 * LQH + b8);
    const uint32_t asBase = smb + 2u * ((uint32_t)HS + (uint32_t)(w * 16 + l15) * LSH + hi8);
    const uint32_t bvBase = smb + 2u * ((uint32_t)HV + (uint32_t)l7 * LSH + b8);

    uint32_t aq[4][4];
    #pragma unroll
    for (int k16 = 0; k16 < 4; ++k16) ldsm4(aq[k16], aqBase + k16 * 32);

    float acc1[16][4];
    #pragma unroll
    for (int ni = 0; ni < 16; ++ni)
        #pragma unroll
        for (int j = 0; j < 4; ++j) acc1[ni][j] = 0.f;

    #pragma unroll
    for (int k16 = 0; k16 < 4; ++k16) {
        #pragma unroll
        for (int ni = 0; ni < 16; ++ni) {
            uint32_t bk[2];
            ldsm2(bk, bkBase + (uint32_t)(ni * 8 * LQH) * 2 + k16 * 32);
            mma_f16(acc1[ni][0], acc1[ni][1], acc1[ni][2], acc1[ni][3],
                    aq[k16][0], aq[k16][1], aq[k16][2], aq[k16][3], bk[0], bk[1]);
        }
    }

    float rs0 = 0.f, rs1 = 0.f;
    #pragma unroll
    for (int ni = 0; ni < 16; ++ni) {
        const int cb = ni * 8 + 2 * t;
        float m0 = (cb     <= r0) ? acc1[ni][0] : 0.f;
        float m1 = (cb + 1 <= r0) ? acc1[ni][1] : 0.f;
        float m2 = (cb     <= r1) ? acc1[ni][2] : 0.f;
        float m3 = (cb + 1 <= r1) ? acc1[ni][3] : 0.f;
        rs0 += m0 + m1;
        rs1 += m2 + m3;
        *(uint32_t*)(smh + HS + r0 * LSH + cb) = pack_h2(m0, m1);
        *(uint32_t*)(smh + HS + r1 * LSH + cb) = pack_h2(m2, m3);
    }
    rs0 += __shfl_xor_sync(0xffffffffu, rs0, 1);
    rs0 += __shfl_xor_sync(0xffffffffu, rs0, 2);
    rs1 += __shfl_xor_sync(0xffffffffu, rs1, 1);
    rs1 += __shfl_xor_sync(0xffffffffu, rs1, 2);
    __syncwarp();
    if (t == 0) {
        smf[FDN + r0] = 1.f / (smf[FDN + r0] + rs0);
        smf[FDN + r1] = 1.f / (smf[FDN + r1] + rs1);
    }
    __syncwarp();
    const float inv0 = smf[FDN + r0];
    const float inv1 = smf[FDN + r1];

    float accO[8][4];
    #pragma unroll
    for (int ni = 0; ni < 8; ++ni)
        #pragma unroll
        for (int j = 0; j < 4; ++j) accO[ni][j] = 0.f;

    #pragma unroll
    for (int k16 = 0; k16 < 4; ++k16) {
        #pragma unroll
        for (int ni = 0; ni < 8; ++ni) {
            uint32_t bp[2];
            ldsm2(bp, bpBase + (uint32_t)(ni * 8 * LQH) * 2 + k16 * 32);
            mma_f16(accO[ni][0], accO[ni][1], accO[ni][2], accO[ni][3],
                    aq[k16][0], aq[k16][1], aq[k16][2], aq[k16][3], bp[0], bp[1]);
        }
    }

    #pragma unroll
    for (int k16 = 0; k16 < 8; ++k16) {
        uint32_t as[4];
        ldsm4(as, asBase + k16 * 32);
        #pragma unroll
        for (int ni = 0; ni < 8; ++ni) {
            uint32_t bv[2];
            ldsm2(bv, bvBase + (uint32_t)(ni * 8 * LSH) * 2 + k16 * 32);
            mma_f16(accO[ni][0], accO[ni][1], accO[ni][2], accO[ni][3],
                    as[0], as[1], as[2], as[3], bv[0], bv[1]);
        }
    }

    #pragma unroll
    for (int ni = 0; ni < 8; ++ni) {
        const int e0 = ni * 8 + 2 * t;
        uint32_t o0 = pack_h2(accO[ni][0] * inv0 + EPSC, accO[ni][1] * inv0 + EPSC);
        uint32_t o1 = pack_h2(accO[ni][2] * inv1 + EPSC, accO[ni][3] * inv1 + EPSC);
        *(uint32_t*)(ga + (size_t)r0 * Dmod + e0) = o0;
        *(uint32_t*)(ga + (size_t)r1 * Dmod + e0) = o1;
    }
}

// ---------------------------------------------------------------------------
extern "C" void kernel_launch(void* const* d_in, const int* in_sizes, int n_in,
                              void* d_out, int out_size) {
    const float* x  = (const float*)d_in[0];
    const float* Wq = (const float*)d_in[1];
    const float* Wk = (const float*)d_in[2];
    const float* Wv = (const float*)d_in[3];
    const float* Wo = (const float*)d_in[4];
    float* out = (float*)d_out;

    cudaFuncSetAttribute(mma_gemm, cudaFuncAttributeMaxDynamicSharedMemorySize,
                         GEMM_SMEM_BYTES);
    cudaFuncSetAttribute(attn_local, cudaFuncAttributeMaxDynamicSharedMemorySize,
                         P1_SMEM_BYTES);
    cudaFuncSetAttribute(attn_out, cudaFuncAttributeMaxDynamicSharedMemorySize,
                         AO_SMEM_BYTES);

    conv_fp16<<<2048, 256>>>((const float4*)x, (const float4*)Wq,
                             (const float4*)Wk, (const float4*)Wv,
                             (const float4*)Wo);
    mma_gemm<<<dim3(Dmod / 128, Mrows / 128, 3), 256, GEMM_SMEM_BYTES>>>(nullptr, 0);
    attn_local<<<NBH * NCH, 128, P1_SMEM_BYTES>>>();
    attn_scan<<<NBH * 4, 256>>>();
    attn_out<<<NBH * NCH, 256, AO_SMEM_BYTES>>>();
    mma_gemm<<<dim3(Dmod / 128, Mrows / 128, 1), 256, GEMM_SMEM_BYTES>>>(out, 1);
}